// round 13
// baseline (speedup 1.0000x reference)
#include <cuda_runtime.h>
#include <cstdint>

// ---------------- problem constants ----------------
#define BB    4
#define NPTS  8192
#define MC    1024
#define NSAMP 16
#define CFEAT 64
#define RAD2  0.25f
#define EPSBN 1e-5f

#define FMA2(acc, a, b) asm("fma.rn.f32x2 %0, %1, %2, %0;" : "+l"(acc) : "l"(a), "l"(b))

// ---------------- mma.sync tf32 helpers ----------------
__device__ __forceinline__ float to_tf32(float x) {
    uint32_t r;
    asm("cvt.rna.tf32.f32 %0, %1;" : "=r"(r) : "f"(x));
    return __uint_as_float(r);
}
__device__ __forceinline__ void mma8(float* d, const uint32_t* a, const uint32_t* b) {
    asm volatile(
        "mma.sync.aligned.m16n8k8.row.col.f32.tf32.tf32.f32 "
        "{%0,%1,%2,%3}, {%4,%5,%6,%7}, {%8,%9}, {%0,%1,%2,%3};"
        : "+f"(d[0]), "+f"(d[1]), "+f"(d[2]), "+f"(d[3])
        : "r"(a[0]), "r"(a[1]), "r"(a[2]), "r"(a[3]), "r"(b[0]), "r"(b[1]));
}

#define TSTR   36
#define ATILE  (256*TSTR)
#define BTILE  (128*TSTR)
#define MMA_SMEM_BYTES ((2*ATILE + 2*BTILE)*4)   // 110592
#define FATT_SMEM_BYTES (37120*4)                // 148480

// ---------------- scratch ----------------
static __device__ float g_featin[(size_t)BB*67*NPTS];
static __device__ float g_y1[(size_t)BB*64*NPTS];
static __device__ float g_y2[(size_t)BB*128*NPTS];
static __device__ float g_y3[(size_t)BB*256*NPTS];
static __device__ float g_nft[(size_t)BB*NPTS*256];
static __device__ int   g_idx1[BB*MC*NSAMP];
static __device__ int   g_idx2[BB*MC*NSAMP];
static __device__ float g_ip[(size_t)BB*259*MC*NSAMP];
static __device__ float g_q[(size_t)BB*8*MC*NSAMP];
static __device__ float g_k[(size_t)BB*8*MC*NSAMP];
static __device__ float g_v[(size_t)BB*256*MC*NSAMP];
static __device__ float g_off[(size_t)BB*256*MC*NSAMP];
static __device__ float g_yf[(size_t)BB*256*MC*NSAMP];
static __device__ float g_pool[(size_t)BB*256*MC];
static __device__ float g_yo[(size_t)BB*512*MC];
static __device__ float g_st1[2*64], g_st2[2*128], g_st3[2*256], g_stf[2*256], g_sto[2*512];
static __device__ float g_sb1[2*64], g_sb2[2*128], g_sb3[2*256], g_sbf[2*256], g_sbo[2*512];

// ---------------- build concat(xyz^T, features) ----------------
__global__ void k_featin(const float* __restrict__ xyz, const float* __restrict__ feats,
                         float* __restrict__ out)
{
    int i = blockIdx.x * 256 + threadIdx.x;
    if (i >= BB*67*NPTS) return;
    int n  = i % NPTS;
    int ch = (i / NPTS) % 67;
    int b  = i / (NPTS*67);
    float v;
    if (ch < 3) v = xyz[((size_t)b*NPTS + n)*3 + ch];
    else        v = feats[((size_t)b*CFEAT + (ch-3))*NPTS + n];
    out[i] = v;
}

// ======== FFMA2 GEMM (MLP stages + Wo) ========
template<int MODE, int STATS>
__global__ void __launch_bounds__(256, 2)
k_gemm2(const float* __restrict__ W, const float* __restrict__ X,
        float* __restrict__ Y, int Cin, int Cout, int NCOL,
        const float* __restrict__ sb, float* __restrict__ stats)
{
    const int b = blockIdx.z;
    const float* Xb = X + (size_t)b * Cin * NCOL;
    float* Yb = Y + (size_t)b * Cout * NCOL;
    const int col0 = blockIdx.x * 128;
    const int row0 = blockIdx.y * 64;
    __shared__ float Wd[2][16][132];
    __shared__ float Xs[2][16][132];
    const int tid = threadIdx.x;
    const int tx = tid & 15, ty = tid >> 4;
    const int wkk = tid & 15, wrb = tid >> 4;
    const int xcol = tid & 127, xkb = tid >> 7;
    float wreg[4];
    float xreg[8];
    const int nch = (Cin + 15) >> 4;

    {
#pragma unroll
        for (int p = 0; p < 4; p++) {
            float w = 0.f;
            if (wkk < Cin) w = W[(size_t)(row0 + wrb + 16*p)*Cin + wkk];
            wreg[p] = w;
        }
#pragma unroll
        for (int t = 0; t < 8; t++) {
            int cg = xkb + 2*t;
            float v = 0.f;
            if (cg < Cin) {
                v = Xb[(size_t)cg*NCOL + col0 + xcol];
                if (MODE == 1) v = fmaxf(fmaf(v, sb[cg], sb[Cin+cg]), 0.f);
            }
            xreg[t] = v;
        }
    }
#pragma unroll
    for (int p = 0; p < 4; p++) *(float2*)&Wd[0][wkk][2*(wrb+16*p)] = make_float2(wreg[p], wreg[p]);
#pragma unroll
    for (int t = 0; t < 8; t++) Xs[0][xkb + 2*t][xcol] = xreg[t];
    __syncthreads();

    unsigned long long acc[4][4];
#pragma unroll
    for (int i = 0; i < 4; i++)
#pragma unroll
        for (int p = 0; p < 4; p++) acc[i][p] = 0ull;

    for (int c = 0; c < nch; c++) {
        int buf = c & 1;
        if (c + 1 < nch) {
            int k0 = (c + 1) << 4;
#pragma unroll
            for (int p = 0; p < 4; p++) {
                float w = 0.f;
                if (k0 + wkk < Cin) w = W[(size_t)(row0 + wrb + 16*p)*Cin + k0 + wkk];
                wreg[p] = w;
            }
#pragma unroll
            for (int t = 0; t < 8; t++) {
                int cg = k0 + xkb + 2*t;
                float v = 0.f;
                if (cg < Cin) {
                    v = Xb[(size_t)cg*NCOL + col0 + xcol];
                    if (MODE == 1) v = fmaxf(fmaf(v, sb[cg], sb[Cin+cg]), 0.f);
                }
                xreg[t] = v;
            }
        }
#pragma unroll
        for (int kk = 0; kk < 16; kk++) {
            ulonglong2 wa = *(const ulonglong2*)&Wd[buf][kk][ty*8];
            ulonglong2 wb = *(const ulonglong2*)&Wd[buf][kk][ty*8 + 4];
            ulonglong2 xa = *(const ulonglong2*)&Xs[buf][kk][tx*4];
            ulonglong2 xb = *(const ulonglong2*)&Xs[buf][kk][64 + tx*4];
            unsigned long long wp[4] = {wa.x, wa.y, wb.x, wb.y};
            unsigned long long xp[4] = {xa.x, xa.y, xb.x, xb.y};
#pragma unroll
            for (int i = 0; i < 4; i++) {
                FMA2(acc[i][0], wp[i], xp[0]);
                FMA2(acc[i][1], wp[i], xp[1]);
                FMA2(acc[i][2], wp[i], xp[2]);
                FMA2(acc[i][3], wp[i], xp[3]);
            }
        }
        if (c + 1 < nch) {
            int nb = buf ^ 1;
#pragma unroll
            for (int p = 0; p < 4; p++) *(float2*)&Wd[nb][wkk][2*(wrb+16*p)] = make_float2(wreg[p], wreg[p]);
#pragma unroll
            for (int t = 0; t < 8; t++) Xs[nb][xkb + 2*t][xcol] = xreg[t];
            __syncthreads();
        }
    }

#pragma unroll
    for (int i = 0; i < 4; i++) {
        int r = row0 + ty*4 + i;
        float rs = 0.f, rq = 0.f;
        float v[8];
#pragma unroll
        for (int p = 0; p < 4; p++) {
            float lo, hi;
            asm("mov.b64 {%0, %1}, %2;" : "=f"(lo), "=f"(hi) : "l"(acc[i][p]));
            v[p*2] = lo; v[p*2+1] = hi;
            rs += lo + hi; rq += lo*lo + hi*hi;
        }
        *(float4*)&Yb[(size_t)r*NCOL + col0 + tx*4]      = make_float4(v[0], v[1], v[2], v[3]);
        *(float4*)&Yb[(size_t)r*NCOL + col0 + 64 + tx*4] = make_float4(v[4], v[5], v[6], v[7]);
        if (STATS) {
#pragma unroll
            for (int o = 8; o > 0; o >>= 1) {
                rs += __shfl_down_sync(0xffffffffu, rs, o);
                rq += __shfl_down_sync(0xffffffffu, rq, o);
            }
            if (tx == 0) { atomicAdd(&stats[r], rs); atomicAdd(&stats[Cout + r], rq); }
        }
    }
}

// ======== mma.sync tf32 core, 64x64 warp tile (fm=4) ========
__device__ __forceinline__ void mma_tile4(const float* As, const float* Bs,
                                          float acc[4][8][4], int warp_m, int warp_n,
                                          int g, int t4)
{
#pragma unroll
    for (int ks = 0; ks < 4; ks++) {
        const int kb = ks * 8;
        uint32_t a[4][4];
#pragma unroll
        for (int fm = 0; fm < 4; fm++) {
            const int rm = warp_m*64 + fm*16;
            a[fm][0] = __float_as_uint(As[(rm + g)*TSTR + kb + t4]);
            a[fm][1] = __float_as_uint(As[(rm + 8 + g)*TSTR + kb + t4]);
            a[fm][2] = __float_as_uint(As[(rm + g)*TSTR + kb + 4 + t4]);
            a[fm][3] = __float_as_uint(As[(rm + 8 + g)*TSTR + kb + 4 + t4]);
        }
#pragma unroll
        for (int fn = 0; fn < 8; fn++) {
            const int rn = warp_n*64 + fn*8;
            uint32_t b[2];
            b[0] = __float_as_uint(Bs[(rn + g)*TSTR + kb + t4]);
            b[1] = __float_as_uint(Bs[(rn + g)*TSTR + kb + 4 + t4]);
            mma8(acc[0][fn], a[0], b);
            mma8(acc[1][fn], a[1], b);
            mma8(acc[2][fn], a[2], b);
            mma8(acc[3][fn], a[3], b);
        }
    }
}

// ======== fused attention: logits + softmax + V*P^T + "-gf" in one kernel ========
// CTA: (b, slot, j-block of 128). smem: K[8][1024], Qt[128][8], m/l, V/P mma tiles.
__global__ void __launch_bounds__(256, 1)
k_fatt(const float* __restrict__ q, const float* __restrict__ k,
       const float* __restrict__ V, const float* __restrict__ ip,
       float* __restrict__ off)
{
    extern __shared__ float sm[];
    float* Ks  = sm;              // [8][1024]
    float* Qt  = sm + 8192;       // [128][8]
    float* msm = sm + 9216;       // [128]
    float* lsm = sm + 9344;       // [128] (holds 1/l)
    float* Vs  = sm + 9472;       // [2][256][36]
    float* Ps  = sm + 27904;      // [2][128][36]

    const int tid = threadIdx.x, wid = tid >> 5, lane = tid & 31;
    const int warp_m = wid >> 1, warp_n = wid & 1;
    const int g = lane >> 2, t4 = lane & 3;
    const int bs = blockIdx.z, slot = bs & 15, b = bs >> 4;
    const int j0 = blockIdx.x * 128;
    const float* qg = q + ((size_t)(b*8)*NSAMP + slot)*MC;
    const float* kg = k + ((size_t)(b*8)*NSAMP + slot)*MC;
    const float* Vb = V + ((size_t)b*256*NSAMP + slot)*MC;

    // phase 0: K (coalesced) + Q transposed (small)
#pragma unroll
    for (int it = 0; it < 8; it++) {
        int idx = tid + 256*it;
        int c8 = idx >> 8, f = idx & 255;
        *(float4*)&Ks[c8*1024 + 4*f] = *(const float4*)&kg[(size_t)c8*(NSAMP*MC) + 4*f];
    }
#pragma unroll
    for (int it = 0; it < 4; it++) {
        int idx = tid + 256*it;
        int j = idx >> 3, c8 = idx & 7;
        Qt[j*8 + c8] = qg[(size_t)c8*(NSAMP*MC) + j0 + j];
    }
    __syncthreads();

    // pass 1: online softmax stats per j (each warp owns 16 j rows)
    {
        float mj[16], lj[16];
#pragma unroll
        for (int jj = 0; jj < 16; jj++) { mj[jj] = -1e30f; lj[jj] = 0.f; }
        for (int it = 0; it < 8; it++) {
            float4 kr[8];
#pragma unroll
            for (int c8 = 0; c8 < 8; c8++)
                kr[c8] = *(const float4*)&Ks[c8*1024 + it*128 + lane*4];
#pragma unroll
            for (int jj = 0; jj < 16; jj++) {
                int j = wid*16 + jj;
                float4 q0 = *(const float4*)&Qt[j*8];
                float4 q1 = *(const float4*)&Qt[j*8 + 4];
                float qv[8] = {q0.x, q0.y, q0.z, q0.w, q1.x, q1.y, q1.z, q1.w};
                float4 a = make_float4(0.f, 0.f, 0.f, 0.f);
#pragma unroll
                for (int c8 = 0; c8 < 8; c8++) {
                    a.x = fmaf(qv[c8], kr[c8].x, a.x);
                    a.y = fmaf(qv[c8], kr[c8].y, a.y);
                    a.z = fmaf(qv[c8], kr[c8].z, a.z);
                    a.w = fmaf(qv[c8], kr[c8].w, a.w);
                }
                float am = fmaxf(fmaxf(a.x, a.y), fmaxf(a.z, a.w));
                float mn = fmaxf(mj[jj], am);
                lj[jj] = lj[jj]*__expf(mj[jj]-mn)
                       + __expf(a.x-mn) + __expf(a.y-mn) + __expf(a.z-mn) + __expf(a.w-mn);
                mj[jj] = mn;
            }
        }
#pragma unroll
        for (int jj = 0; jj < 16; jj++) {
            float M = mj[jj];
#pragma unroll
            for (int o = 16; o > 0; o >>= 1) M = fmaxf(M, __shfl_xor_sync(0xffffffffu, M, o));
            float lp = lj[jj] * __expf(mj[jj] - M);
#pragma unroll
            for (int o = 16; o > 0; o >>= 1) lp += __shfl_xor_sync(0xffffffffu, lp, o);
            if (lane == 0) {
                int j = wid*16 + jj;
                msm[j] = M;
                lsm[j] = 1.f / lp;
            }
        }
    }
    __syncthreads();

    // pass 2: chunked V * P^T with tf32 mma
    float acc[4][8][4];
#pragma unroll
    for (int i = 0; i < 4; i++)
#pragma unroll
        for (int j = 0; j < 8; j++)
#pragma unroll
            for (int p = 0; p < 4; p++) acc[i][j][p] = 0.f;

    float4 vreg[8];
    auto loadV = [&](int ch) {
#pragma unroll
        for (int it = 0; it < 8; it++) {
            int idx = tid + 256*it;
            int row = idx >> 3, f = idx & 7;
            vreg[it] = *(const float4*)&Vb[(size_t)row*(NSAMP*MC) + ch*32 + 4*f];
        }
    };
    auto storeV = [&](int buf) {
#pragma unroll
        for (int it = 0; it < 8; it++) {
            int idx = tid + 256*it;
            int row = idx >> 3, f = idx & 7;
            *(float4*)&Vs[buf*9216 + row*36 + 4*f] =
                make_float4(to_tf32(vreg[it].x), to_tf32(vreg[it].y),
                            to_tf32(vreg[it].z), to_tf32(vreg[it].w));
        }
    };
    auto computeP = [&](int ch, int buf) {
        float kr[8];
#pragma unroll
        for (int c8 = 0; c8 < 8; c8++) kr[c8] = Ks[c8*1024 + ch*32 + lane];
#pragma unroll
        for (int jj = 0; jj < 16; jj++) {
            int j = wid*16 + jj;
            float4 q0 = *(const float4*)&Qt[j*8];
            float4 q1 = *(const float4*)&Qt[j*8 + 4];
            float s = q0.x*kr[0] + q0.y*kr[1] + q0.z*kr[2] + q0.w*kr[3]
                    + q1.x*kr[4] + q1.y*kr[5] + q1.z*kr[6] + q1.w*kr[7];
            float p = __expf(s - msm[j]) * lsm[j];
            Ps[buf*4608 + j*36 + lane] = to_tf32(p);
        }
    };

    loadV(0);
    storeV(0);
    computeP(0, 0);
    __syncthreads();

    for (int ch = 0; ch < 32; ch++) {
        const int buf = ch & 1;
        if (ch + 1 < 32) loadV(ch + 1);
        mma_tile4(&Vs[buf*9216], &Ps[buf*4608], acc, warp_m, warp_n, g, t4);
        if (ch + 1 < 32) {
            __syncthreads();
            storeV(buf ^ 1);
            computeP(ch + 1, buf ^ 1);
            __syncthreads();
        }
    }

    // epilogue: subtract group_features, store off
#pragma unroll
    for (int fm = 0; fm < 4; fm++) {
        const int r0 = warp_m*64 + fm*16 + g;
        const int r1 = r0 + 8;
        const float* ip0 = ip + (((size_t)b*259 + r0)*NSAMP + slot)*MC;
        const float* ip1 = ip + (((size_t)b*259 + r1)*NSAMP + slot)*MC;
        float* of0 = off + (((size_t)b*256 + r0)*NSAMP + slot)*MC;
        float* of1 = off + (((size_t)b*256 + r1)*NSAMP + slot)*MC;
#pragma unroll
        for (int fn = 0; fn < 8; fn++) {
            const int jj = j0 + warp_n*64 + fn*8 + 2*t4;
            float2 ga = *(const float2*)&ip0[jj];
            float2 gb = *(const float2*)&ip1[jj];
            *(float2*)&of0[jj] = make_float2(acc[fm][fn][0] - ga.x, acc[fm][fn][1] - ga.y);
            *(float2*)&of1[jj] = make_float2(acc[fm][fn][2] - gb.x, acc[fm][fn][3] - gb.y);
        }
    }
}

// ======== NN: Y[b,o,col] = sum_k W[o,k] X[b,k,col] (tf32 mma; Wv / Wf) ========
template<int STATS>
__global__ void __launch_bounds__(256, 1)
k_mma_nn(const float* __restrict__ W, const float* __restrict__ X,
         float* __restrict__ Y, int Cin, int Cout, float* __restrict__ stats)
{
    extern __shared__ float sm[];
    const int tid = threadIdx.x, wid = tid >> 5, lane = tid & 31;
    const int warp_m = wid >> 1, warp_n = wid & 1;
    const int g = lane >> 2, t4 = lane & 3;
    const int b = blockIdx.z;
    const int NCOL = MC * NSAMP;
    const float* Xb = X + (size_t)b * Cin * NCOL;
    const int ncol0 = blockIdx.x * 128;
    const bool al4 = (Cin & 3) == 0;

    float acc[4][8][4];
#pragma unroll
    for (int i = 0; i < 4; i++)
#pragma unroll
        for (int j = 0; j < 8; j++)
#pragma unroll
            for (int p = 0; p < 4; p++) acc[i][j][p] = 0.f;

    float4 pa[8], pb[4];
    const int nch = (Cin + 31) >> 5;

    auto loadA = [&](int k0) {
#pragma unroll
        for (int it = 0; it < 8; it++) {
            int idx = tid + 256*it, row = idx >> 3, f = idx & 7;
            int k = k0 + 4*f;
            const float* wr = &W[(size_t)row*Cin];
            float4 w4;
            if (al4 && k + 3 < Cin) w4 = *(const float4*)&wr[k];
            else {
                w4.x = (k+0 < Cin) ? wr[k+0] : 0.f;
                w4.y = (k+1 < Cin) ? wr[k+1] : 0.f;
                w4.z = (k+2 < Cin) ? wr[k+2] : 0.f;
                w4.w = (k+3 < Cin) ? wr[k+3] : 0.f;
            }
            pa[it] = w4;
        }
    };
    auto loadB = [&](int k0) {
#pragma unroll
        for (int it = 0; it < 4; it++) {
            int kk = k0 + lane;
            int n4 = (tid >> 5) + 8*it;
            float4 x4 = make_float4(0.f, 0.f, 0.f, 0.f);
            if (kk < Cin) x4 = *(const float4*)&Xb[(size_t)kk*NCOL + ncol0 + 4*n4];
            pb[it] = x4;
        }
    };
    auto storeT = [&](int buf) {
        float* As = sm + buf*ATILE;
        float* Bs = sm + 2*ATILE + buf*BTILE;
#pragma unroll
        for (int it = 0; it < 8; it++) {
            int idx = tid + 256*it, row = idx >> 3, f = idx & 7;
            *(float4*)&As[row*TSTR + 4*f] = make_float4(to_tf32(pa[it].x), to_tf32(pa[it].y),
                                                        to_tf32(pa[it].z), to_tf32(pa[it].w));
        }
#pragma unroll
        for (int it = 0; it < 4; it++) {
            int kk = lane;
            int n4 = (tid >> 5) + 8*it;
            Bs[(4*n4 + 0)*TSTR + kk] = to_tf32(pb[it].x);
            Bs[(4*n4 + 1)*TSTR + kk] = to_tf32(pb[it].y);
            Bs[(4*n4 + 2)*TSTR + kk] = to_tf32(pb[it].z);
            Bs[(4*n4 + 3)*TSTR + kk] = to_tf32(pb[it].w);
        }
    };

    loadA(0); loadB(0);
    storeT(0);
    __syncthreads();

    for (int c = 0; c < nch; c++) {
        const int buf = c & 1;
        if (c + 1 < nch) { loadA((c+1)*32); loadB((c+1)*32); }
        mma_tile4(sm + buf*ATILE, sm + 2*ATILE + buf*BTILE, acc, warp_m, warp_n, g, t4);
        if (c + 1 < nch) {
            __syncthreads();
            storeT(buf ^ 1);
            __syncthreads();
        }
    }

#pragma unroll
    for (int fm = 0; fm < 4; fm++) {
        const int r0 = warp_m*64 + fm*16 + g;
        const int r1 = r0 + 8;
        float* y0 = Y + ((size_t)b*Cout + r0)*NCOL + ncol0;
        float* y1 = Y + ((size_t)b*Cout + r1)*NCOL + ncol0;
        float s0 = 0.f, q0 = 0.f, s1 = 0.f, q1 = 0.f;
#pragma unroll
        for (int fn = 0; fn < 8; fn++) {
            const int jj = warp_n*64 + fn*8 + 2*t4;
            float d0 = acc[fm][fn][0], d1 = acc[fm][fn][1];
            float d2 = acc[fm][fn][2], d3 = acc[fm][fn][3];
            *(float2*)&y0[jj] = make_float2(d0, d1);
            *(float2*)&y1[jj] = make_float2(d2, d3);
            if (STATS) {
                s0 += d0 + d1; q0 += d0*d0 + d1*d1;
                s1 += d2 + d3; q1 += d2*d2 + d3*d3;
            }
        }
        if (STATS) {
#pragma unroll
            for (int o = 1; o < 4; o <<= 1) {
                s0 += __shfl_xor_sync(0xffffffffu, s0, o);
                q0 += __shfl_xor_sync(0xffffffffu, q0, o);
                s1 += __shfl_xor_sync(0xffffffffu, s1, o);
                q1 += __shfl_xor_sync(0xffffffffu, q1, o);
            }
            if (t4 == 0) {
                atomicAdd(&stats[r0], s0); atomicAdd(&stats[Cout + r0], q0);
                atomicAdd(&stats[r1], s1); atomicAdd(&stats[Cout + r1], q1);
            }
        }
    }
}

// ---------------- fused q+k projection ----------------
__global__ void k_qk(const float* __restrict__ Wq, const float* __restrict__ Wk,
                     const float* __restrict__ X, float* __restrict__ q,
                     float* __restrict__ k)
{
    const int b = blockIdx.y;
    const int NCOL = MC*NSAMP;
    const float* Xb = X + (size_t)b * 259 * NCOL;
    __shared__ float Ws[16][260];
    for (int i = threadIdx.x; i < 8*259; i += 128) {
        int r = i / 259, c = i % 259;
        Ws[r][c] = Wq[i];
        Ws[r+8][c] = Wk[i];
    }
    __syncthreads();
    int col = blockIdx.x * 128 + threadIdx.x;
    float acc[16];
#pragma unroll
    for (int o = 0; o < 16; o++) acc[o] = 0.f;
    for (int c = 0; c < 259; c++) {
        float xv = Xb[(size_t)c*NCOL + col];
#pragma unroll
        for (int o = 0; o < 16; o++) acc[o] = fmaf(Ws[o][c], xv, acc[o]);
    }
#pragma unroll
    for (int o = 0; o < 8; o++) {
        q[((size_t)b*8 + o)*NCOL + col] = acc[o];
        k[((size_t)b*8 + o)*NCOL + col] = acc[o+8];
    }
}

// ---------------- BN finalize ----------------
__global__ void k_fin(const float* __restrict__ stats, const float* __restrict__ g,
                      const float* __restrict__ be, float* __restrict__ sb,
                      int Cc, float invcnt)
{
    int c = blockIdx.x * 64 + threadIdx.x;
    if (c >= Cc) return;
    float mu  = stats[c] * invcnt;
    float var = stats[Cc + c] * invcnt - mu*mu;
    float s = g[c] * rsqrtf(var + EPSBN);
    sb[c] = s;
    sb[Cc + c] = be[c] - mu * s;
}

// ---------------- ball query ----------------
__global__ void k_bq(const float* __restrict__ src, const float* __restrict__ ctr,
                     int* __restrict__ out, int NSRC)
{
    int gw = (blockIdx.x * blockDim.x + threadIdx.x) >> 5;
    int lane = threadIdx.x & 31;
    __shared__ int lists[8][NSAMP];
    int* list = lists[threadIdx.x >> 5];
    if (gw >= BB*MC) return;
    int b = gw / MC, m = gw % MC;
    float cx = ctr[((size_t)b*MC + m)*3 + 0];
    float cy = ctr[((size_t)b*MC + m)*3 + 1];
    float cz = ctr[((size_t)b*MC + m)*3 + 2];
    int count = 0;
    for (int base = 0; base < NSRC; base += 32) {
        int n = base + lane;
        bool ok = false;
        if (n < NSRC) {
            float dx = src[((size_t)b*NSRC + n)*3 + 0] - cx;
            float dy = src[((size_t)b*NSRC + n)*3 + 1] - cy;
            float dz = src[((size_t)b*NSRC + n)*3 + 2] - cz;
            ok = (dx*dx + dy*dy + dz*dz) < RAD2;
        }
        unsigned mk = __ballot_sync(0xffffffffu, ok);
        if (ok) {
            int pos = count + __popc(mk & ((1u << lane) - 1u));
            if (pos < NSAMP) list[pos] = n;
        }
        count += __popc(mk);
        if (count >= NSAMP) break;
    }
    __syncwarp();
    if (lane < NSAMP) {
        int v;
        if (count == 0) v = 0;
        else v = (lane < count) ? list[lane] : list[0];
        out[((size_t)b*MC + m)*NSAMP + lane] = v;
    }
}

// ---------------- new_features transpose with affine+relu ----------------
__global__ void k_nft(const float* __restrict__ y3, const float* __restrict__ sb3,
                      float* __restrict__ nft)
{
    int b = blockIdx.z;
    int n0 = blockIdx.x * 32, c0 = blockIdx.y * 32;
    __shared__ float t[32][33];
#pragma unroll
    for (int i = 0; i < 4; i++) {
        int c = c0 + threadIdx.y + i*8;
        int n = n0 + threadIdx.x;
        float v = y3[((size_t)b*256 + c)*NPTS + n];
        v = fmaxf(fmaf(v, sb3[c], sb3[256 + c]), 0.f);
        t[threadIdx.y + i*8][threadIdx.x] = v;
    }
    __syncthreads();
#pragma unroll
    for (int i = 0; i < 4; i++) {
        int n = n0 + threadIdx.y + i*8;
        int c = c0 + threadIdx.x;
        nft[((size_t)b*NPTS + n)*256 + c] = t[threadIdx.x][threadIdx.y + i*8];
    }
}

// ---------------- build ip ----------------
__global__ void k_ip(const float* __restrict__ nft, const int* __restrict__ idx1,
                     const int* __restrict__ idx2, const float* __restrict__ xyz,
                     const float* __restrict__ ctr, float* __restrict__ ip)
{
    int bz = blockIdx.x;
    int cblk = bz & 31;
    int slot = (bz >> 5) & 15;
    int b    = bz >> 9;
    __shared__ float s[256][33];
    int warp = threadIdx.x >> 5, lane = threadIdx.x & 31;
#pragma unroll
    for (int w = 0; w < 4; w++) {
        int center = cblk*32 + warp*4 + w;
        int id = idx1[((size_t)b*MC + center)*NSAMP + slot];
        const float* srcp = nft + ((size_t)b*NPTS + id)*256;
#pragma unroll
        for (int t = 0; t < 8; t++) s[lane + t*32][warp*4 + w] = srcp[lane + t*32];
    }
    __syncthreads();
    int center = threadIdx.x & 31, chb = threadIdx.x >> 5;
#pragma unroll
    for (int t = 0; t < 32; t++) {
        int ch = chb + t*8;
        ip[(((size_t)b*259 + ch)*NSAMP + slot)*MC + cblk*32 + center] = s[ch][center];
    }
    if (threadIdx.x < 96) {
        int d = threadIdx.x / 32;
        int cc = threadIdx.x & 31;
        int ctr_i = cblk*32 + cc;
        int i1 = idx1[((size_t)b*MC + ctr_i)*NSAMP + slot];
        int i2 = idx2[((size_t)b*MC + ctr_i)*NSAMP + slot];
        float r = ctr[((size_t)b*MC + i2)*3 + d] - xyz[((size_t)b*NPTS + i1)*3 + d];
        ip[(((size_t)b*259 + 256 + d)*NSAMP + slot)*MC + ctr_i] = r;
    }
}

// ---------------- relu(affine(yf)) + gf residual, max-pool over slot ----------------
__global__ void k_pool(const float* __restrict__ yf, const float* __restrict__ sbf,
                       const float* __restrict__ ip, float* __restrict__ pool)
{
    int i = blockIdx.x * 256 + threadIdx.x;
    if (i >= BB*256*MC) return;
    int center = i & (MC-1);
    int c = (i >> 10) & 255;
    int b = i >> 18;
    float s = sbf[c], bi = sbf[256 + c];
    float mx = -1e30f;
#pragma unroll
    for (int slot = 0; slot < NSAMP; slot++) {
        float v = fmaxf(fmaf(yf[(((size_t)b*256 + c)*NSAMP + slot)*MC + center], s, bi), 0.f);
        v += ip[(((size_t)b*259 + c)*NSAMP + slot)*MC + center];
        mx = fmaxf(mx, v);
    }
    pool[((size_t)b*256 + c)*MC + center] = mx;
}

// ---------------- final ----------------
__global__ void k_final(const float* __restrict__ yo, const float* __restrict__ sbo,
                        const float* __restrict__ ctr, float* __restrict__ out, int has_ctr)
{
    int off0 = has_ctr ? BB*MC*3 : 0;
    int total = off0 + BB*512*MC;
    int i = blockIdx.x * 256 + threadIdx.x;
    if (i >= total) return;
    if (i < off0) { out[i] = ctr[i]; return; }
    int j = i - off0;
    int ch = (j >> 10) & 511;
    out[i] = fmaxf(fmaf(yo[j], sbo[ch], sbo[512 + ch]), 0.f);
}

// ---------------- host launch ----------------
extern "C" void kernel_launch(void* const* d_in, const int* in_sizes, int n_in,
                              void* d_out, int out_size)
{
    const float* xyz   = (const float*)d_in[0];
    const float* feats = (const float*)d_in[1];
    const float* ctr   = (const float*)d_in[2];
    const float* W1 = (const float*)d_in[3];
    const float* g1 = (const float*)d_in[4];
    const float* b1 = (const float*)d_in[5];
    const float* W2 = (const float*)d_in[6];
    const float* g2 = (const float*)d_in[7];
    const float* b2 = (const float*)d_in[8];
    const float* W3 = (const float*)d_in[9];
    const float* g3 = (const float*)d_in[10];
    const float* b3 = (const float*)d_in[11];
    const float* Wq = (const float*)d_in[12];
    const float* Wk = (const float*)d_in[13];
    const float* Wv = (const float*)d_in[14];
    const float* Wf = (const float*)d_in[15];
    const float* gp = (const float*)d_in[16];
    const float* bp = (const float*)d_in[17];
    const float* Wo = (const float*)d_in[18];
    const float* go = (const float*)d_in[19];
    const float* bo = (const float*)d_in[20];
    float* outp = (float*)d_out;

    float *featin, *y1, *y2, *y3, *nft, *ip, *qb, *kb, *vb, *offb, *yf, *pool, *yo;
    int *idx1, *idx2;
    float *st1, *st2, *st3, *stf, *sto, *sb1, *sb2, *sb3, *sbf, *sbo;
    cudaGetSymbolAddress((void**)&featin, g_featin);
    cudaGetSymbolAddress((void**)&y1, g_y1);
    cudaGetSymbolAddress((void**)&y2, g_y2);
    cudaGetSymbolAddress((void**)&y3, g_y3);
    cudaGetSymbolAddress((void**)&nft, g_nft);
    cudaGetSymbolAddress((void**)&idx1, g_idx1);
    cudaGetSymbolAddress((void**)&idx2, g_idx2);
    cudaGetSymbolAddress((void**)&ip, g_ip);
    cudaGetSymbolAddress((void**)&qb, g_q);
    cudaGetSymbolAddress((void**)&kb, g_k);
    cudaGetSymbolAddress((void**)&vb, g_v);
    cudaGetSymbolAddress((void**)&offb, g_off);
    cudaGetSymbolAddress((void**)&yf, g_yf);
    cudaGetSymbolAddress((void**)&pool, g_pool);
    cudaGetSymbolAddress((void**)&yo, g_yo);
    cudaGetSymbolAddress((void**)&st1, g_st1);
    cudaGetSymbolAddress((void**)&st2, g_st2);
    cudaGetSymbolAddress((void**)&st3, g_st3);
    cudaGetSymbolAddress((void**)&stf, g_stf);
    cudaGetSymbolAddress((void**)&sto, g_sto);
    cudaGetSymbolAddress((void**)&sb1, g_sb1);
    cudaGetSymbolAddress((void**)&sb2, g_sb2);
    cudaGetSymbolAddress((void**)&sb3, g_sb3);
    cudaGetSymbolAddress((void**)&sbf, g_sbf);
    cudaGetSymbolAddress((void**)&sbo, g_sbo);

    cudaFuncSetAttribute(k_fatt, cudaFuncAttributeMaxDynamicSharedMemorySize, FATT_SMEM_BYTES);
    cudaFuncSetAttribute(k_mma_nn<0>, cudaFuncAttributeMaxDynamicSharedMemorySize, MMA_SMEM_BYTES);
    cudaFuncSetAttribute(k_mma_nn<1>, cudaFuncAttributeMaxDynamicSharedMemorySize, MMA_SMEM_BYTES);

    cudaMemsetAsync(st1, 0, sizeof(float)*2*64,  0);
    cudaMemsetAsync(st2, 0, sizeof(float)*2*128, 0);
    cudaMemsetAsync(st3, 0, sizeof(float)*2*256, 0);
    cudaMemsetAsync(stf, 0, sizeof(float)*2*256, 0);
    cudaMemsetAsync(sto, 0, sizeof(float)*2*512, 0);

    k_featin<<<(BB*67*NPTS + 255)/256, 256>>>(xyz, feats, featin);

    // MLP (FFMA2, fp32 — trunk precision)
    k_gemm2<0,1><<<dim3(NPTS/128, 1, BB), 256>>>(W1, featin, y1, 67, 64, NPTS, nullptr, st1);
    k_fin<<<1, 64>>>(st1, g1, b1, sb1, 64, 1.f/(BB*NPTS));
    k_gemm2<1,1><<<dim3(NPTS/128, 2, BB), 256>>>(W2, y1, y2, 64, 128, NPTS, sb1, st2);
    k_fin<<<2, 64>>>(st2, g2, b2, sb2, 128, 1.f/(BB*NPTS));
    k_gemm2<1,1><<<dim3(NPTS/128, 4, BB), 256>>>(W3, y2, y3, 128, 256, NPTS, sb2, st3);
    k_fin<<<4, 64>>>(st3, g3, b3, sb3, 256, 1.f/(BB*NPTS));

    k_nft<<<dim3(NPTS/32, 8, BB), dim3(32, 8)>>>(y3, sb3, nft);

    k_bq<<<(BB*MC*32 + 255)/256, 256>>>(xyz, ctr, idx1, NPTS);
    k_bq<<<(BB*MC*32 + 255)/256, 256>>>(ctr, ctr, idx2, MC);

    k_ip<<<BB*16*32, 256>>>(nft, idx1, idx2, xyz, ctr, ip);

    // q, k (fused FFMA), v (tf32 mma, 256-row tile)
    k_qk<<<dim3(MC*NSAMP/128, BB), 128>>>(Wq, Wk, ip, qb, kb);
    k_mma_nn<0><<<dim3(128, 1, BB), 256, MMA_SMEM_BYTES>>>(Wv, ip, vb, 259, 256, nullptr);

    // fused attention: softmax + V P^T + "-gf" in one pass (no P materialization)
    k_fatt<<<dim3(8, 1, BB*NSAMP), 256, FATT_SMEM_BYTES>>>(qb, kb, vb, ip, offb);

    // Wf (tf32 mma + BN stats, 256-row tile), pool
    k_mma_nn<1><<<dim3(128, 1, BB), 256, MMA_SMEM_BYTES>>>(Wf, offb, yf, 256, 256, stf);
    k_fin<<<4, 64>>>(stf, gp, bp, sbf, 256, 1.f/(BB*MC*NSAMP));
    k_pool<<<(BB*256*MC + 255)/256, 256>>>(yf, sbf, ip, pool);

    // output conv (FFMA2, fp32)
    k_gemm2<0,1><<<dim3(MC/128, 8, BB), 256>>>(Wo, pool, yo, 256, 512, MC, nullptr, sto);
    k_fin<<<8, 64>>>(sto, go, bo, sbo, 512, 1.f/(BB*MC));

    int has_ctr = (out_size == BB*MC*3 + BB*512*MC) ? 1 : 0;
    int total = (has_ctr ? BB*MC*3 : 0) + BB*512*MC;
    k_final<<<(total + 255)/256, 256>>>(yo, sbo, ctr, outp, has_ctr);
}

// round 14
// speedup vs baseline: 1.1359x; 1.1359x over previous
#include <cuda_runtime.h>
#include <cstdint>

// ---------------- problem constants ----------------
#define BB    4
#define NPTS  8192
#define MC    1024
#define NSAMP 16
#define CFEAT 64
#define RAD2  0.25f
#define EPSBN 1e-5f

#define FMA2(acc, a, b) asm("fma.rn.f32x2 %0, %1, %2, %0;" : "+l"(acc) : "l"(a), "l"(b))

// ---------------- mma.sync tf32 helpers ----------------
__device__ __forceinline__ float to_tf32(float x) {
    uint32_t r;
    asm("cvt.rna.tf32.f32 %0, %1;" : "=r"(r) : "f"(x));
    return __uint_as_float(r);
}
__device__ __forceinline__ void mma8(float* d, const uint32_t* a, const uint32_t* b) {
    asm volatile(
        "mma.sync.aligned.m16n8k8.row.col.f32.tf32.tf32.f32 "
        "{%0,%1,%2,%3}, {%4,%5,%6,%7}, {%8,%9}, {%0,%1,%2,%3};"
        : "+f"(d[0]), "+f"(d[1]), "+f"(d[2]), "+f"(d[3])
        : "r"(a[0]), "r"(a[1]), "r"(a[2]), "r"(a[3]), "r"(b[0]), "r"(b[1]));
}

#define TSTR   36
#define ATILE  (256*TSTR)
#define BTILE  (128*TSTR)
#define MMA_SMEM_BYTES ((2*ATILE + 2*BTILE)*4)   // 110592

// ---------------- scratch ----------------
static __device__ float g_featin[(size_t)BB*67*NPTS];
static __device__ float g_y1[(size_t)BB*64*NPTS];
static __device__ float g_y2[(size_t)BB*128*NPTS];
static __device__ float g_y3[(size_t)BB*256*NPTS];
static __device__ float g_nft[(size_t)BB*NPTS*256];
static __device__ int   g_idx1[BB*MC*NSAMP];
static __device__ int   g_idx2[BB*MC*NSAMP];
static __device__ float g_ip[(size_t)BB*259*MC*NSAMP];
static __device__ float g_q[(size_t)BB*8*MC*NSAMP];
static __device__ float g_k[(size_t)BB*8*MC*NSAMP];
static __device__ float g_P[(size_t)BB*NSAMP*MC*MC];
static __device__ float g_v[(size_t)BB*256*MC*NSAMP];
static __device__ float g_off[(size_t)BB*256*MC*NSAMP];
static __device__ float g_yf[(size_t)BB*256*MC*NSAMP];
static __device__ float g_pool[(size_t)BB*256*MC];
static __device__ float g_yo[(size_t)BB*512*MC];
static __device__ float g_st1[2*64], g_st2[2*128], g_st3[2*256], g_stf[2*256], g_sto[2*512];
static __device__ float g_sb1[2*64], g_sb2[2*128], g_sb3[2*256], g_sbf[2*256], g_sbo[2*512];

// ---------------- build concat(xyz^T, features) ----------------
__global__ void k_featin(const float* __restrict__ xyz, const float* __restrict__ feats,
                         float* __restrict__ out)
{
    int i = blockIdx.x * 256 + threadIdx.x;
    if (i >= BB*67*NPTS) return;
    int n  = i % NPTS;
    int ch = (i / NPTS) % 67;
    int b  = i / (NPTS*67);
    float v;
    if (ch < 3) v = xyz[((size_t)b*NPTS + n)*3 + ch];
    else        v = feats[((size_t)b*CFEAT + (ch-3))*NPTS + n];
    out[i] = v;
}

// ======== FFMA2 GEMM (MLP stages + Wo) ========
template<int MODE, int STATS>
__global__ void __launch_bounds__(256, 2)
k_gemm2(const float* __restrict__ W, const float* __restrict__ X,
        float* __restrict__ Y, int Cin, int Cout, int NCOL,
        const float* __restrict__ sb, float* __restrict__ stats)
{
    const int b = blockIdx.z;
    const float* Xb = X + (size_t)b * Cin * NCOL;
    float* Yb = Y + (size_t)b * Cout * NCOL;
    const int col0 = blockIdx.x * 128;
    const int row0 = blockIdx.y * 64;
    __shared__ float Wd[2][16][132];
    __shared__ float Xs[2][16][132];
    const int tid = threadIdx.x;
    const int tx = tid & 15, ty = tid >> 4;
    const int wkk = tid & 15, wrb = tid >> 4;
    const int xcol = tid & 127, xkb = tid >> 7;
    float wreg[4];
    float xreg[8];
    const int nch = (Cin + 15) >> 4;

    {
#pragma unroll
        for (int p = 0; p < 4; p++) {
            float w = 0.f;
            if (wkk < Cin) w = W[(size_t)(row0 + wrb + 16*p)*Cin + wkk];
            wreg[p] = w;
        }
#pragma unroll
        for (int t = 0; t < 8; t++) {
            int cg = xkb + 2*t;
            float v = 0.f;
            if (cg < Cin) {
                v = Xb[(size_t)cg*NCOL + col0 + xcol];
                if (MODE == 1) v = fmaxf(fmaf(v, sb[cg], sb[Cin+cg]), 0.f);
            }
            xreg[t] = v;
        }
    }
#pragma unroll
    for (int p = 0; p < 4; p++) *(float2*)&Wd[0][wkk][2*(wrb+16*p)] = make_float2(wreg[p], wreg[p]);
#pragma unroll
    for (int t = 0; t < 8; t++) Xs[0][xkb + 2*t][xcol] = xreg[t];
    __syncthreads();

    unsigned long long acc[4][4];
#pragma unroll
    for (int i = 0; i < 4; i++)
#pragma unroll
        for (int p = 0; p < 4; p++) acc[i][p] = 0ull;

    for (int c = 0; c < nch; c++) {
        int buf = c & 1;
        if (c + 1 < nch) {
            int k0 = (c + 1) << 4;
#pragma unroll
            for (int p = 0; p < 4; p++) {
                float w = 0.f;
                if (k0 + wkk < Cin) w = W[(size_t)(row0 + wrb + 16*p)*Cin + k0 + wkk];
                wreg[p] = w;
            }
#pragma unroll
            for (int t = 0; t < 8; t++) {
                int cg = k0 + xkb + 2*t;
                float v = 0.f;
                if (cg < Cin) {
                    v = Xb[(size_t)cg*NCOL + col0 + xcol];
                    if (MODE == 1) v = fmaxf(fmaf(v, sb[cg], sb[Cin+cg]), 0.f);
                }
                xreg[t] = v;
            }
        }
#pragma unroll
        for (int kk = 0; kk < 16; kk++) {
            ulonglong2 wa = *(const ulonglong2*)&Wd[buf][kk][ty*8];
            ulonglong2 wb = *(const ulonglong2*)&Wd[buf][kk][ty*8 + 4];
            ulonglong2 xa = *(const ulonglong2*)&Xs[buf][kk][tx*4];
            ulonglong2 xb = *(const ulonglong2*)&Xs[buf][kk][64 + tx*4];
            unsigned long long wp[4] = {wa.x, wa.y, wb.x, wb.y};
            unsigned long long xp[4] = {xa.x, xa.y, xb.x, xb.y};
#pragma unroll
            for (int i = 0; i < 4; i++) {
                FMA2(acc[i][0], wp[i], xp[0]);
                FMA2(acc[i][1], wp[i], xp[1]);
                FMA2(acc[i][2], wp[i], xp[2]);
                FMA2(acc[i][3], wp[i], xp[3]);
            }
        }
        if (c + 1 < nch) {
            int nb = buf ^ 1;
#pragma unroll
            for (int p = 0; p < 4; p++) *(float2*)&Wd[nb][wkk][2*(wrb+16*p)] = make_float2(wreg[p], wreg[p]);
#pragma unroll
            for (int t = 0; t < 8; t++) Xs[nb][xkb + 2*t][xcol] = xreg[t];
            __syncthreads();
        }
    }

#pragma unroll
    for (int i = 0; i < 4; i++) {
        int r = row0 + ty*4 + i;
        float rs = 0.f, rq = 0.f;
        float v[8];
#pragma unroll
        for (int p = 0; p < 4; p++) {
            float lo, hi;
            asm("mov.b64 {%0, %1}, %2;" : "=f"(lo), "=f"(hi) : "l"(acc[i][p]));
            v[p*2] = lo; v[p*2+1] = hi;
            rs += lo + hi; rq += lo*lo + hi*hi;
        }
        *(float4*)&Yb[(size_t)r*NCOL + col0 + tx*4]      = make_float4(v[0], v[1], v[2], v[3]);
        *(float4*)&Yb[(size_t)r*NCOL + col0 + 64 + tx*4] = make_float4(v[4], v[5], v[6], v[7]);
        if (STATS) {
#pragma unroll
            for (int o = 8; o > 0; o >>= 1) {
                rs += __shfl_down_sync(0xffffffffu, rs, o);
                rq += __shfl_down_sync(0xffffffffu, rq, o);
            }
            if (tx == 0) { atomicAdd(&stats[r], rs); atomicAdd(&stats[Cout + r], rq); }
        }
    }
}

// ======== mma.sync tf32 core, 64x64 warp tile (fm=4) ========
__device__ __forceinline__ void mma_tile4(const float* As, const float* Bs,
                                          float acc[4][8][4], int warp_m, int warp_n,
                                          int g, int t4)
{
#pragma unroll
    for (int ks = 0; ks < 4; ks++) {
        const int kb = ks * 8;
        uint32_t a[4][4];
#pragma unroll
        for (int fm = 0; fm < 4; fm++) {
            const int rm = warp_m*64 + fm*16;
            a[fm][0] = __float_as_uint(As[(rm + g)*TSTR + kb + t4]);
            a[fm][1] = __float_as_uint(As[(rm + 8 + g)*TSTR + kb + t4]);
            a[fm][2] = __float_as_uint(As[(rm + g)*TSTR + kb + 4 + t4]);
            a[fm][3] = __float_as_uint(As[(rm + 8 + g)*TSTR + kb + 4 + t4]);
        }
#pragma unroll
        for (int fn = 0; fn < 8; fn++) {
            const int rn = warp_n*64 + fn*8;
            uint32_t b[2];
            b[0] = __float_as_uint(Bs[(rn + g)*TSTR + kb + t4]);
            b[1] = __float_as_uint(Bs[(rn + g)*TSTR + kb + 4 + t4]);
            mma8(acc[0][fn], a[0], b);
            mma8(acc[1][fn], a[1], b);
            mma8(acc[2][fn], a[2], b);
            mma8(acc[3][fn], a[3], b);
        }
    }
}

// ======== attfeat (NT): off[c,j] = sum_n V[c,n] P[j,n] - gf[c,j] ========
// CTA tile: 256 c x 128 j.
__global__ void __launch_bounds__(256, 1)
k_mma_nt(const float* __restrict__ V, const float* __restrict__ P,
         const float* __restrict__ ip, float* __restrict__ off)
{
    extern __shared__ float sm[];
    const int tid = threadIdx.x, wid = tid >> 5, lane = tid & 31;
    const int warp_m = wid >> 1, warp_n = wid & 1;
    const int g = lane >> 2, t4 = lane & 3;
    const int bs = blockIdx.z, slot = bs & 15, b = bs >> 4;
    const float* Vb = V + ((size_t)b*256*NSAMP + slot)*MC;
    const float* Pb = P + ((size_t)(b*NSAMP + slot))*MC*MC;
    const int j0 = blockIdx.x * 128;

    float acc[4][8][4];
#pragma unroll
    for (int i = 0; i < 4; i++)
#pragma unroll
        for (int j = 0; j < 8; j++)
#pragma unroll
            for (int p = 0; p < 4; p++) acc[i][j][p] = 0.f;

    float4 pa[8], pb[4];
    auto loadA = [&](int n0) {
#pragma unroll
        for (int it = 0; it < 8; it++) {
            int idx = tid + 256*it, row = idx >> 3, f = idx & 7;
            pa[it] = *(const float4*)&Vb[(size_t)row*(NSAMP*MC) + n0 + 4*f];
        }
    };
    auto loadB = [&](int n0) {
#pragma unroll
        for (int it = 0; it < 4; it++) {
            int idx = tid + 256*it, row = idx >> 3, f = idx & 7;
            pb[it] = *(const float4*)&Pb[(size_t)(j0+row)*MC + n0 + 4*f];
        }
    };
    auto storeT = [&](int buf) {
        float* As = sm + buf*ATILE;
        float* Bs = sm + 2*ATILE + buf*BTILE;
#pragma unroll
        for (int it = 0; it < 8; it++) {
            int idx = tid + 256*it, row = idx >> 3, f = idx & 7;
            *(float4*)&As[row*TSTR + 4*f] = make_float4(to_tf32(pa[it].x), to_tf32(pa[it].y),
                                                        to_tf32(pa[it].z), to_tf32(pa[it].w));
        }
#pragma unroll
        for (int it = 0; it < 4; it++) {
            int idx = tid + 256*it, row = idx >> 3, f = idx & 7;
            *(float4*)&Bs[row*TSTR + 4*f] = make_float4(to_tf32(pb[it].x), to_tf32(pb[it].y),
                                                        to_tf32(pb[it].z), to_tf32(pb[it].w));
        }
    };

    loadA(0); loadB(0);
    storeT(0);
    __syncthreads();

    const int nch = MC / 32;
    for (int c = 0; c < nch; c++) {
        const int buf = c & 1;
        if (c + 1 < nch) { loadA((c+1)*32); loadB((c+1)*32); }
        mma_tile4(sm + buf*ATILE, sm + 2*ATILE + buf*BTILE, acc, warp_m, warp_n, g, t4);
        if (c + 1 < nch) {
            __syncthreads();
            storeT(buf ^ 1);
            __syncthreads();
        }
    }

#pragma unroll
    for (int fm = 0; fm < 4; fm++) {
        const int r0 = warp_m*64 + fm*16 + g;
        const int r1 = r0 + 8;
        const float* ip0 = ip + (((size_t)b*259 + r0)*NSAMP + slot)*MC;
        const float* ip1 = ip + (((size_t)b*259 + r1)*NSAMP + slot)*MC;
        float* of0 = off + (((size_t)b*256 + r0)*NSAMP + slot)*MC;
        float* of1 = off + (((size_t)b*256 + r1)*NSAMP + slot)*MC;
#pragma unroll
        for (int fn = 0; fn < 8; fn++) {
            const int jj = j0 + warp_n*64 + fn*8 + 2*t4;
            float2 ga = *(const float2*)&ip0[jj];
            float2 gb = *(const float2*)&ip1[jj];
            *(float2*)&of0[jj] = make_float2(acc[fm][fn][0] - ga.x, acc[fm][fn][1] - ga.y);
            *(float2*)&of1[jj] = make_float2(acc[fm][fn][2] - gb.x, acc[fm][fn][3] - gb.y);
        }
    }
}

// ======== NN: Y[b,o,col] = sum_k W[o,k] X[b,k,col] (tf32 mma; Wv / Wf) ========
template<int STATS>
__global__ void __launch_bounds__(256, 1)
k_mma_nn(const float* __restrict__ W, const float* __restrict__ X,
         float* __restrict__ Y, int Cin, int Cout, float* __restrict__ stats)
{
    extern __shared__ float sm[];
    const int tid = threadIdx.x, wid = tid >> 5, lane = tid & 31;
    const int warp_m = wid >> 1, warp_n = wid & 1;
    const int g = lane >> 2, t4 = lane & 3;
    const int b = blockIdx.z;
    const int NCOL = MC * NSAMP;
    const float* Xb = X + (size_t)b * Cin * NCOL;
    const int ncol0 = blockIdx.x * 128;
    const bool al4 = (Cin & 3) == 0;

    float acc[4][8][4];
#pragma unroll
    for (int i = 0; i < 4; i++)
#pragma unroll
        for (int j = 0; j < 8; j++)
#pragma unroll
            for (int p = 0; p < 4; p++) acc[i][j][p] = 0.f;

    float4 pa[8], pb[4];
    const int nch = (Cin + 31) >> 5;

    auto loadA = [&](int k0) {
#pragma unroll
        for (int it = 0; it < 8; it++) {
            int idx = tid + 256*it, row = idx >> 3, f = idx & 7;
            int k = k0 + 4*f;
            const float* wr = &W[(size_t)row*Cin];
            float4 w4;
            if (al4 && k + 3 < Cin) w4 = *(const float4*)&wr[k];
            else {
                w4.x = (k+0 < Cin) ? wr[k+0] : 0.f;
                w4.y = (k+1 < Cin) ? wr[k+1] : 0.f;
                w4.z = (k+2 < Cin) ? wr[k+2] : 0.f;
                w4.w = (k+3 < Cin) ? wr[k+3] : 0.f;
            }
            pa[it] = w4;
        }
    };
    auto loadB = [&](int k0) {
#pragma unroll
        for (int it = 0; it < 4; it++) {
            int kk = k0 + lane;
            int n4 = (tid >> 5) + 8*it;
            float4 x4 = make_float4(0.f, 0.f, 0.f, 0.f);
            if (kk < Cin) x4 = *(const float4*)&Xb[(size_t)kk*NCOL + ncol0 + 4*n4];
            pb[it] = x4;
        }
    };
    auto storeT = [&](int buf) {
        float* As = sm + buf*ATILE;
        float* Bs = sm + 2*ATILE + buf*BTILE;
#pragma unroll
        for (int it = 0; it < 8; it++) {
            int idx = tid + 256*it, row = idx >> 3, f = idx & 7;
            *(float4*)&As[row*TSTR + 4*f] = make_float4(to_tf32(pa[it].x), to_tf32(pa[it].y),
                                                        to_tf32(pa[it].z), to_tf32(pa[it].w));
        }
#pragma unroll
        for (int it = 0; it < 4; it++) {
            int kk = lane;
            int n4 = (tid >> 5) + 8*it;
            Bs[(4*n4 + 0)*TSTR + kk] = to_tf32(pb[it].x);
            Bs[(4*n4 + 1)*TSTR + kk] = to_tf32(pb[it].y);
            Bs[(4*n4 + 2)*TSTR + kk] = to_tf32(pb[it].z);
            Bs[(4*n4 + 3)*TSTR + kk] = to_tf32(pb[it].w);
        }
    };

    loadA(0); loadB(0);
    storeT(0);
    __syncthreads();

    for (int c = 0; c < nch; c++) {
        const int buf = c & 1;
        if (c + 1 < nch) { loadA((c+1)*32); loadB((c+1)*32); }
        mma_tile4(sm + buf*ATILE, sm + 2*ATILE + buf*BTILE, acc, warp_m, warp_n, g, t4);
        if (c + 1 < nch) {
            __syncthreads();
            storeT(buf ^ 1);
            __syncthreads();
        }
    }

#pragma unroll
    for (int fm = 0; fm < 4; fm++) {
        const int r0 = warp_m*64 + fm*16 + g;
        const int r1 = r0 + 8;
        float* y0 = Y + ((size_t)b*Cout + r0)*NCOL + ncol0;
        float* y1 = Y + ((size_t)b*Cout + r1)*NCOL + ncol0;
        float s0 = 0.f, q0 = 0.f, s1 = 0.f, q1 = 0.f;
#pragma unroll
        for (int fn = 0; fn < 8; fn++) {
            const int jj = warp_n*64 + fn*8 + 2*t4;
            float d0 = acc[fm][fn][0], d1 = acc[fm][fn][1];
            float d2 = acc[fm][fn][2], d3 = acc[fm][fn][3];
            *(float2*)&y0[jj] = make_float2(d0, d1);
            *(float2*)&y1[jj] = make_float2(d2, d3);
            if (STATS) {
                s0 += d0 + d1; q0 += d0*d0 + d1*d1;
                s1 += d2 + d3; q1 += d2*d2 + d3*d3;
            }
        }
        if (STATS) {
#pragma unroll
            for (int o = 1; o < 4; o <<= 1) {
                s0 += __shfl_xor_sync(0xffffffffu, s0, o);
                q0 += __shfl_xor_sync(0xffffffffu, q0, o);
                s1 += __shfl_xor_sync(0xffffffffu, s1, o);
                q1 += __shfl_xor_sync(0xffffffffu, q1, o);
            }
            if (t4 == 0) {
                atomicAdd(&stats[r0], s0); atomicAdd(&stats[Cout + r0], q0);
                atomicAdd(&stats[r1], s1); atomicAdd(&stats[Cout + r1], q1);
            }
        }
    }
}

// ---------------- fused q+k projection ----------------
__global__ void k_qk(const float* __restrict__ Wq, const float* __restrict__ Wk,
                     const float* __restrict__ X, float* __restrict__ q,
                     float* __restrict__ k)
{
    const int b = blockIdx.y;
    const int NCOL = MC*NSAMP;
    const float* Xb = X + (size_t)b * 259 * NCOL;
    __shared__ float Ws[16][260];
    for (int i = threadIdx.x; i < 8*259; i += 128) {
        int r = i / 259, c = i % 259;
        Ws[r][c] = Wq[i];
        Ws[r+8][c] = Wk[i];
    }
    __syncthreads();
    int col = blockIdx.x * 128 + threadIdx.x;
    float acc[16];
#pragma unroll
    for (int o = 0; o < 16; o++) acc[o] = 0.f;
    for (int c = 0; c < 259; c++) {
        float xv = Xb[(size_t)c*NCOL + col];
#pragma unroll
        for (int o = 0; o < 16; o++) acc[o] = fmaf(Ws[o][c], xv, acc[o]);
    }
#pragma unroll
    for (int o = 0; o < 8; o++) {
        q[((size_t)b*8 + o)*NCOL + col] = acc[o];
        k[((size_t)b*8 + o)*NCOL + col] = acc[o+8];
    }
}

// ---------------- BN finalize ----------------
__global__ void k_fin(const float* __restrict__ stats, const float* __restrict__ g,
                      const float* __restrict__ be, float* __restrict__ sb,
                      int Cc, float invcnt)
{
    int c = blockIdx.x * 64 + threadIdx.x;
    if (c >= Cc) return;
    float mu  = stats[c] * invcnt;
    float var = stats[Cc + c] * invcnt - mu*mu;
    float s = g[c] * rsqrtf(var + EPSBN);
    sb[c] = s;
    sb[Cc + c] = be[c] - mu * s;
}

// ---------------- ball query ----------------
__global__ void k_bq(const float* __restrict__ src, const float* __restrict__ ctr,
                     int* __restrict__ out, int NSRC)
{
    int gw = (blockIdx.x * blockDim.x + threadIdx.x) >> 5;
    int lane = threadIdx.x & 31;
    __shared__ int lists[8][NSAMP];
    int* list = lists[threadIdx.x >> 5];
    if (gw >= BB*MC) return;
    int b = gw / MC, m = gw % MC;
    float cx = ctr[((size_t)b*MC + m)*3 + 0];
    float cy = ctr[((size_t)b*MC + m)*3 + 1];
    float cz = ctr[((size_t)b*MC + m)*3 + 2];
    int count = 0;
    for (int base = 0; base < NSRC; base += 32) {
        int n = base + lane;
        bool ok = false;
        if (n < NSRC) {
            float dx = src[((size_t)b*NSRC + n)*3 + 0] - cx;
            float dy = src[((size_t)b*NSRC + n)*3 + 1] - cy;
            float dz = src[((size_t)b*NSRC + n)*3 + 2] - cz;
            ok = (dx*dx + dy*dy + dz*dz) < RAD2;
        }
        unsigned mk = __ballot_sync(0xffffffffu, ok);
        if (ok) {
            int pos = count + __popc(mk & ((1u << lane) - 1u));
            if (pos < NSAMP) list[pos] = n;
        }
        count += __popc(mk);
        if (count >= NSAMP) break;
    }
    __syncwarp();
    if (lane < NSAMP) {
        int v;
        if (count == 0) v = 0;
        else v = (lane < count) ? list[lane] : list[0];
        out[((size_t)b*MC + m)*NSAMP + lane] = v;
    }
}

// ---------------- new_features transpose with affine+relu ----------------
__global__ void k_nft(const float* __restrict__ y3, const float* __restrict__ sb3,
                      float* __restrict__ nft)
{
    int b = blockIdx.z;
    int n0 = blockIdx.x * 32, c0 = blockIdx.y * 32;
    __shared__ float t[32][33];
#pragma unroll
    for (int i = 0; i < 4; i++) {
        int c = c0 + threadIdx.y + i*8;
        int n = n0 + threadIdx.x;
        float v = y3[((size_t)b*256 + c)*NPTS + n];
        v = fmaxf(fmaf(v, sb3[c], sb3[256 + c]), 0.f);
        t[threadIdx.y + i*8][threadIdx.x] = v;
    }
    __syncthreads();
#pragma unroll
    for (int i = 0; i < 4; i++) {
        int n = n0 + threadIdx.y + i*8;
        int c = c0 + threadIdx.x;
        nft[((size_t)b*NPTS + n)*256 + c] = t[threadIdx.x][threadIdx.y + i*8];
    }
}

// ---------------- build ip ----------------
__global__ void k_ip(const float* __restrict__ nft, const int* __restrict__ idx1,
                     const int* __restrict__ idx2, const float* __restrict__ xyz,
                     const float* __restrict__ ctr, float* __restrict__ ip)
{
    int bz = blockIdx.x;
    int cblk = bz & 31;
    int slot = (bz >> 5) & 15;
    int b    = bz >> 9;
    __shared__ float s[256][33];
    int warp = threadIdx.x >> 5, lane = threadIdx.x & 31;
#pragma unroll
    for (int w = 0; w < 4; w++) {
        int center = cblk*32 + warp*4 + w;
        int id = idx1[((size_t)b*MC + center)*NSAMP + slot];
        const float* srcp = nft + ((size_t)b*NPTS + id)*256;
#pragma unroll
        for (int t = 0; t < 8; t++) s[lane + t*32][warp*4 + w] = srcp[lane + t*32];
    }
    __syncthreads();
    int center = threadIdx.x & 31, chb = threadIdx.x >> 5;
#pragma unroll
    for (int t = 0; t < 32; t++) {
        int ch = chb + t*8;
        ip[(((size_t)b*259 + ch)*NSAMP + slot)*MC + cblk*32 + center] = s[ch][center];
    }
    if (threadIdx.x < 96) {
        int d = threadIdx.x / 32;
        int cc = threadIdx.x & 31;
        int ctr_i = cblk*32 + cc;
        int i1 = idx1[((size_t)b*MC + ctr_i)*NSAMP + slot];
        int i2 = idx2[((size_t)b*MC + ctr_i)*NSAMP + slot];
        float r = ctr[((size_t)b*MC + i2)*3 + d] - xyz[((size_t)b*NPTS + i1)*3 + d];
        ip[(((size_t)b*259 + 256 + d)*NSAMP + slot)*MC + ctr_i] = r;
    }
}

// ---------------- attention: K tiled in smem, warp-per-column softmax ----------------
// CTA: one (b, slot, block of 64 j). K[8][1024] cached in smem (32 KB).
__global__ void __launch_bounds__(256)
k_att(const float* __restrict__ q, const float* __restrict__ k,
      float* __restrict__ P)
{
    __shared__ float ks[8][MC];
    int bx = blockIdx.x;
    int jblk = bx & 15;           // MC/64
    int slot = (bx >> 4) & 15;
    int b = bx >> 8;
    int wid = threadIdx.x >> 5, lane = threadIdx.x & 31;
    const float* qb = q + ((size_t)b*8*NSAMP + slot)*MC;
    const float* kb = k + ((size_t)b*8*NSAMP + slot)*MC;

    // cooperative load K[8][1024] (2048 float4)
#pragma unroll
    for (int i = 0; i < 8; i++) {
        int idx = threadIdx.x + 256*i;
        int c = idx >> 8, f = idx & 255;
        *(float4*)&ks[c][4*f] = *(const float4*)&kb[(size_t)c*NSAMP*MC + 4*f];
    }
    __syncthreads();

    for (int jj = 0; jj < 8; jj++) {
        int j = jblk*64 + wid*8 + jj;
        float tq = (lane < 8) ? qb[(size_t)lane*NSAMP*MC + j] : 0.f;
        float qv[8];
#pragma unroll
        for (int c = 0; c < 8; c++) qv[c] = __shfl_sync(0xffffffffu, tq, c);

        float4 s4[8];
#pragma unroll
        for (int it = 0; it < 8; it++) {
            int n = it*128 + lane*4;
            float4 a = make_float4(0.f, 0.f, 0.f, 0.f);
#pragma unroll
            for (int c = 0; c < 8; c++) {
                float4 kv = *(const float4*)&ks[c][n];
                a.x = fmaf(kv.x, qv[c], a.x);
                a.y = fmaf(kv.y, qv[c], a.y);
                a.z = fmaf(kv.z, qv[c], a.z);
                a.w = fmaf(kv.w, qv[c], a.w);
            }
            s4[it] = a;
        }
        float mx = -1e30f;
#pragma unroll
        for (int it = 0; it < 8; it++)
            mx = fmaxf(mx, fmaxf(fmaxf(s4[it].x, s4[it].y), fmaxf(s4[it].z, s4[it].w)));
#pragma unroll
        for (int o = 16; o > 0; o >>= 1) mx = fmaxf(mx, __shfl_xor_sync(0xffffffffu, mx, o));
        float sum = 0.f;
#pragma unroll
        for (int it = 0; it < 8; it++) {
            s4[it].x = __expf(s4[it].x - mx);
            s4[it].y = __expf(s4[it].y - mx);
            s4[it].z = __expf(s4[it].z - mx);
            s4[it].w = __expf(s4[it].w - mx);
            sum += s4[it].x + s4[it].y + s4[it].z + s4[it].w;
        }
#pragma unroll
        for (int o = 16; o > 0; o >>= 1) sum += __shfl_xor_sync(0xffffffffu, sum, o);
        float inv = 1.f / sum;
        float* Pr = P + (((size_t)(b*NSAMP + slot))*MC + j)*MC;
#pragma unroll
        for (int it = 0; it < 8; it++) {
            *(float4*)&Pr[it*128 + lane*4] = make_float4(s4[it].x*inv, s4[it].y*inv,
                                                         s4[it].z*inv, s4[it].w*inv);
        }
    }
}

// ---------------- relu(affine(yf)) + gf residual, max-pool over slot ----------------
__global__ void k_pool(const float* __restrict__ yf, const float* __restrict__ sbf,
                       const float* __restrict__ ip, float* __restrict__ pool)
{
    int i = blockIdx.x * 256 + threadIdx.x;
    if (i >= BB*256*MC) return;
    int center = i & (MC-1);
    int c = (i >> 10) & 255;
    int b = i >> 18;
    float s = sbf[c], bi = sbf[256 + c];
    float mx = -1e30f;
#pragma unroll
    for (int slot = 0; slot < NSAMP; slot++) {
        float v = fmaxf(fmaf(yf[(((size_t)b*256 + c)*NSAMP + slot)*MC + center], s, bi), 0.f);
        v += ip[(((size_t)b*259 + c)*NSAMP + slot)*MC + center];
        mx = fmaxf(mx, v);
    }
    pool[((size_t)b*256 + c)*MC + center] = mx;
}

// ---------------- final ----------------
__global__ void k_final(const float* __restrict__ yo, const float* __restrict__ sbo,
                        const float* __restrict__ ctr, float* __restrict__ out, int has_ctr)
{
    int off0 = has_ctr ? BB*MC*3 : 0;
    int total = off0 + BB*512*MC;
    int i = blockIdx.x * 256 + threadIdx.x;
    if (i >= total) return;
    if (i < off0) { out[i] = ctr[i]; return; }
    int j = i - off0;
    int ch = (j >> 10) & 511;
    out[i] = fmaxf(fmaf(yo[j], sbo[ch], sbo[512 + ch]), 0.f);
}

// ---------------- host launch ----------------
extern "C" void kernel_launch(void* const* d_in, const int* in_sizes, int n_in,
                              void* d_out, int out_size)
{
    const float* xyz   = (const float*)d_in[0];
    const float* feats = (const float*)d_in[1];
    const float* ctr   = (const float*)d_in[2];
    const float* W1 = (const float*)d_in[3];
    const float* g1 = (const float*)d_in[4];
    const float* b1 = (const float*)d_in[5];
    const float* W2 = (const float*)d_in[6];
    const float* g2 = (const float*)d_in[7];
    const float* b2 = (const float*)d_in[8];
    const float* W3 = (const float*)d_in[9];
    const float* g3 = (const float*)d_in[10];
    const float* b3 = (const float*)d_in[11];
    const float* Wq = (const float*)d_in[12];
    const float* Wk = (const float*)d_in[13];
    const float* Wv = (const float*)d_in[14];
    const float* Wf = (const float*)d_in[15];
    const float* gp = (const float*)d_in[16];
    const float* bp = (const float*)d_in[17];
    const float* Wo = (const float*)d_in[18];
    const float* go = (const float*)d_in[19];
    const float* bo = (const float*)d_in[20];
    float* outp = (float*)d_out;

    float *featin, *y1, *y2, *y3, *nft, *ip, *qb, *kb, *vb, *Pb, *offb, *yf, *pool, *yo;
    int *idx1, *idx2;
    float *st1, *st2, *st3, *stf, *sto, *sb1, *sb2, *sb3, *sbf, *sbo;
    cudaGetSymbolAddress((void**)&featin, g_featin);
    cudaGetSymbolAddress((void**)&y1, g_y1);
    cudaGetSymbolAddress((void**)&y2, g_y2);
    cudaGetSymbolAddress((void**)&y3, g_y3);
    cudaGetSymbolAddress((void**)&nft, g_nft);
    cudaGetSymbolAddress((void**)&idx1, g_idx1);
    cudaGetSymbolAddress((void**)&idx2, g_idx2);
    cudaGetSymbolAddress((void**)&ip, g_ip);
    cudaGetSymbolAddress((void**)&qb, g_q);
    cudaGetSymbolAddress((void**)&kb, g_k);
    cudaGetSymbolAddress((void**)&vb, g_v);
    cudaGetSymbolAddress((void**)&Pb, g_P);
    cudaGetSymbolAddress((void**)&offb, g_off);
    cudaGetSymbolAddress((void**)&yf, g_yf);
    cudaGetSymbolAddress((void**)&pool, g_pool);
    cudaGetSymbolAddress((void**)&yo, g_yo);
    cudaGetSymbolAddress((void**)&st1, g_st1);
    cudaGetSymbolAddress((void**)&st2, g_st2);
    cudaGetSymbolAddress((void**)&st3, g_st3);
    cudaGetSymbolAddress((void**)&stf, g_stf);
    cudaGetSymbolAddress((void**)&sto, g_sto);
    cudaGetSymbolAddress((void**)&sb1, g_sb1);
    cudaGetSymbolAddress((void**)&sb2, g_sb2);
    cudaGetSymbolAddress((void**)&sb3, g_sb3);
    cudaGetSymbolAddress((void**)&sbf, g_sbf);
    cudaGetSymbolAddress((void**)&sbo, g_sbo);

    cudaFuncSetAttribute(k_mma_nt, cudaFuncAttributeMaxDynamicSharedMemorySize, MMA_SMEM_BYTES);
    cudaFuncSetAttribute(k_mma_nn<0>, cudaFuncAttributeMaxDynamicSharedMemorySize, MMA_SMEM_BYTES);
    cudaFuncSetAttribute(k_mma_nn<1>, cudaFuncAttributeMaxDynamicSharedMemorySize, MMA_SMEM_BYTES);

    cudaMemsetAsync(st1, 0, sizeof(float)*2*64,  0);
    cudaMemsetAsync(st2, 0, sizeof(float)*2*128, 0);
    cudaMemsetAsync(st3, 0, sizeof(float)*2*256, 0);
    cudaMemsetAsync(stf, 0, sizeof(float)*2*256, 0);
    cudaMemsetAsync(sto, 0, sizeof(float)*2*512, 0);

    k_featin<<<(BB*67*NPTS + 255)/256, 256>>>(xyz, feats, featin);

    // MLP (FFMA2, fp32 — trunk precision)
    k_gemm2<0,1><<<dim3(NPTS/128, 1, BB), 256>>>(W1, featin, y1, 67, 64, NPTS, nullptr, st1);
    k_fin<<<1, 64>>>(st1, g1, b1, sb1, 64, 1.f/(BB*NPTS));
    k_gemm2<1,1><<<dim3(NPTS/128, 2, BB), 256>>>(W2, y1, y2, 64, 128, NPTS, sb1, st2);
    k_fin<<<2, 64>>>(st2, g2, b2, sb2, 128, 1.f/(BB*NPTS));
    k_gemm2<1,1><<<dim3(NPTS/128, 4, BB), 256>>>(W3, y2, y3, 128, 256, NPTS, sb2, st3);
    k_fin<<<4, 64>>>(st3, g3, b3, sb3, 256, 1.f/(BB*NPTS));

    k_nft<<<dim3(NPTS/32, 8, BB), dim3(32, 8)>>>(y3, sb3, nft);

    k_bq<<<(BB*MC*32 + 255)/256, 256>>>(xyz, ctr, idx1, NPTS);
    k_bq<<<(BB*MC*32 + 255)/256, 256>>>(ctr, ctr, idx2, MC);

    k_ip<<<BB*16*32, 256>>>(nft, idx1, idx2, xyz, ctr, ip);

    // q, k (fused FFMA), v (tf32 mma, 256-row tile)
    k_qk<<<dim3(MC*NSAMP/128, BB), 128>>>(Wq, Wk, ip, qb, kb);
    k_mma_nn<0><<<dim3(128, 1, BB), 256, MMA_SMEM_BYTES>>>(Wv, ip, vb, 259, 256, nullptr);

    // attention: K-tiled warp softmax, then V P^T (tf32 mma, 256-row tile)
    k_att<<<BB*NSAMP*(MC/64), 256>>>(qb, kb, Pb);
    k_mma_nt<<<dim3(8, 1, BB*NSAMP), 256, MMA_SMEM_BYTES>>>(vb, Pb, ip, offb);

    // Wf (tf32 mma + BN stats, 256-row tile), pool
    k_mma_nn<1><<<dim3(128, 1, BB), 256, MMA_SMEM_BYTES>>>(Wf, offb, yf, 256, 256, stf);
    k_fin<<<4, 64>>>(stf, gp, bp, sbf, 256, 1.f/(BB*MC*NSAMP));
    k_pool<<<(BB*256*MC + 255)/256, 256>>>(yf, sbf, ip, pool);

    // output conv (FFMA2, fp32)
    k_gemm2<0,1><<<dim3(MC/128, 8, BB), 256>>>(Wo, pool, yo, 256, 512, MC, nullptr, sto);
    k_fin<<<8, 64>>>(sto, go, bo, sbo, 512, 1.f/(BB*MC));

    int has_ctr = (out_size == BB*MC*3 + BB*512*MC) ? 1 : 0;
    int total = (has_ctr ? BB*MC*3 : 0) + BB*512*MC;
    k_final<<<(total + 255)/256, 256>>>(yo, sbo, ctr, outp, has_ctr);
}